// round 1
// baseline (speedup 1.0000x reference)
#include <cuda_runtime.h>
#include <math.h>

#define D_MODEL 4096
#define N_EXP   64
#define ROWS    16384          // 4 * 4096
#define LN_EPS  1e-5f
#define TM      64             // rows per CTA
#define KC      64             // k-chunk
#define NCTA    (ROWS / TM)    // 256
#define THREADS 256

// ---- device scratch (no allocations allowed) ----
__device__ float g_gw[N_EXP * D_MODEL];   // gamma ⊙ W
__device__ float g_c1[N_EXP];             // sum_k gamma_k * W[e][k]
__device__ float g_c2[N_EXP];             // sum_k beta_k * W[e][k] + b[e]
__device__ float g_part[NCTA * N_EXP];    // per-CTA softmax-weight partial sums

// Output layout (fp32, concatenated flat):
//   [0, 1048576)           sparse_w   (16384 x 64)
//   [1048576, 1081344)     indices    (16384 x 2), cast to float
//   [1081344]              lb_loss
#define OUT_IDX_OFF 1048576
#define OUT_LB_OFF  1081344

// ---------------- packed f32x2 helpers ----------------
__device__ __forceinline__ unsigned long long pack2(float lo, float hi) {
    unsigned long long r;
    asm("mov.b64 %0, {%1, %2};" : "=l"(r) : "f"(lo), "f"(hi));
    return r;
}
__device__ __forceinline__ unsigned long long fma2(unsigned long long a,
                                                   unsigned long long b,
                                                   unsigned long long c) {
    unsigned long long r;
    asm("fma.rn.f32x2 %0, %1, %2, %3;" : "=l"(r) : "l"(a), "l"(b), "l"(c));
    return r;
}
__device__ __forceinline__ void unpack2(unsigned long long v, float& lo, float& hi) {
    asm("mov.b64 {%0, %1}, %2;" : "=f"(lo), "=f"(hi) : "l"(v));
}

// ---------------- prep: gw = gamma ⊙ W, c1/c2 constants ----------------
__global__ void prep_kernel(const float* __restrict__ W,
                            const float* __restrict__ gamma,
                            const float* __restrict__ beta,
                            const float* __restrict__ b) {
    int e = blockIdx.x;
    int t = threadIdx.x;
    float a1 = 0.f, a2 = 0.f;
    const float* Wr = W + e * D_MODEL;
    for (int k = t; k < D_MODEL; k += blockDim.x) {
        float w = Wr[k];
        float gwv = gamma[k] * w;
        g_gw[e * D_MODEL + k] = gwv;
        a1 += gwv;
        a2 += beta[k] * w;
    }
    __shared__ float s1[256], s2[256];
    s1[t] = a1; s2[t] = a2;
    __syncthreads();
    for (int s = 128; s > 0; s >>= 1) {
        if (t < s) { s1[t] += s1[t + s]; s2[t] += s2[t + s]; }
        __syncthreads();
    }
    if (t == 0) { g_c1[e] = s1[0]; g_c2[e] = s2[0] + b[e]; }
}

// ---------------- main fused kernel ----------------
struct SmemA {
    float xs[KC][TM + 4];        // transposed: xs[kk][row]
    float ws[KC][N_EXP + 4];     // transposed: ws[kk][expert]
};
struct SmemB {
    float lgs[TM][N_EXP];        // logits tile
    float lbp[8][N_EXP];         // per-warp lb partials
};

__global__ __launch_bounds__(THREADS)
void main_kernel(const float* __restrict__ x, float* __restrict__ out) {
    __shared__ union { SmemA a; SmemB b; } u;
    __shared__ float srow[TM], ssrow[TM], smu[TM], srstd[TM];

    const int t    = threadIdx.x;
    const int row0 = blockIdx.x * TM;

    // loader mapping: 4 threads per row/expert-row
    const int lrow = t >> 2;         // 0..63
    const int l4   = t & 3;

    // compute mapping: 16x16 thread grid -> 4 rows x 4 experts per thread
    const int tr = t & 15;
    const int tc = t >> 4;
    const int rb = tr * 4;
    const int eb = tc * 4;

    unsigned long long accA[4], accB[4];   // accA: rows(rb,rb+1); accB: rows(rb+2,rb+3)
    #pragma unroll
    for (int i = 0; i < 4; ++i) { accA[i] = 0ull; accB[i] = 0ull; }

    float ls = 0.f, lss = 0.f;
    const float* xrow = x + (size_t)(row0 + lrow) * D_MODEL;
    const float* wrow = g_gw + (size_t)lrow * D_MODEL;

    for (int chunk = 0; chunk < D_MODEL / KC; ++chunk) {
        const int k0 = chunk * KC;
        // load X chunk (transposed into smem) + accumulate sum/sumsq
        #pragma unroll
        for (int j = 0; j < 4; ++j) {
            int col = l4 * 16 + j * 4;
            float4 v = *(const float4*)(xrow + k0 + col);
            u.a.xs[col + 0][lrow] = v.x;
            u.a.xs[col + 1][lrow] = v.y;
            u.a.xs[col + 2][lrow] = v.z;
            u.a.xs[col + 3][lrow] = v.w;
            ls  += v.x + v.y + v.z + v.w;
            lss += v.x * v.x + v.y * v.y + v.z * v.z + v.w * v.w;
        }
        // load gW chunk (transposed)
        #pragma unroll
        for (int j = 0; j < 4; ++j) {
            int col = l4 * 16 + j * 4;
            float4 v = *(const float4*)(wrow + k0 + col);
            u.a.ws[col + 0][lrow] = v.x;
            u.a.ws[col + 1][lrow] = v.y;
            u.a.ws[col + 2][lrow] = v.z;
            u.a.ws[col + 3][lrow] = v.w;
        }
        __syncthreads();

        #pragma unroll 8
        for (int kk = 0; kk < KC; ++kk) {
            float4 xv = *(const float4*)&u.a.xs[kk][rb];
            float4 wv = *(const float4*)&u.a.ws[kk][eb];
            unsigned long long xA = pack2(xv.x, xv.y);
            unsigned long long xB = pack2(xv.z, xv.w);
            unsigned long long w0 = pack2(wv.x, wv.x);
            unsigned long long w1 = pack2(wv.y, wv.y);
            unsigned long long w2 = pack2(wv.z, wv.z);
            unsigned long long w3 = pack2(wv.w, wv.w);
            accA[0] = fma2(xA, w0, accA[0]);  accB[0] = fma2(xB, w0, accB[0]);
            accA[1] = fma2(xA, w1, accA[1]);  accB[1] = fma2(xB, w1, accB[1]);
            accA[2] = fma2(xA, w2, accA[2]);  accB[2] = fma2(xB, w2, accB[2]);
            accA[3] = fma2(xA, w3, accA[3]);  accB[3] = fma2(xB, w3, accB[3]);
        }
        __syncthreads();
    }

    // reduce sum/sumsq within each loader quad (4 consecutive lanes)
    ls  += __shfl_xor_sync(0xffffffffu, ls, 1);
    ls  += __shfl_xor_sync(0xffffffffu, ls, 2);
    lss += __shfl_xor_sync(0xffffffffu, lss, 1);
    lss += __shfl_xor_sync(0xffffffffu, lss, 2);
    if (l4 == 0) { srow[lrow] = ls; ssrow[lrow] = lss; }
    __syncthreads();

    if (t < TM) {
        float mu  = srow[t] * (1.f / D_MODEL);
        float var = ssrow[t] * (1.f / D_MODEL) - mu * mu;
        smu[t]   = mu;
        srstd[t] = rsqrtf(var + LN_EPS);
    }
    __syncthreads();

    // logits into shared (union flips to SmemB: all SmemA reads are behind syncs)
    {
        float mu0 = smu[rb + 0], mu1 = smu[rb + 1], mu2 = smu[rb + 2], mu3 = smu[rb + 3];
        float rs0 = srstd[rb + 0], rs1 = srstd[rb + 1], rs2 = srstd[rb + 2], rs3 = srstd[rb + 3];
        #pragma unroll
        for (int i = 0; i < 4; ++i) {
            float c1 = g_c1[eb + i];
            float c2 = g_c2[eb + i];
            float a0, a1, a2, a3;
            unpack2(accA[i], a0, a1);
            unpack2(accB[i], a2, a3);
            u.b.lgs[rb + 0][eb + i] = rs0 * (a0 - mu0 * c1) + c2;
            u.b.lgs[rb + 1][eb + i] = rs1 * (a1 - mu1 * c1) + c2;
            u.b.lgs[rb + 2][eb + i] = rs2 * (a2 - mu2 * c1) + c2;
            u.b.lgs[rb + 3][eb + i] = rs3 * (a3 - mu3 * c1) + c2;
        }
    }
    __syncthreads();

    // softmax + top-2 + scatter + renorm : one warp handles 8 rows
    const int w    = t >> 5;
    const int lane = t & 31;
    float lb0 = 0.f, lb1 = 0.f;

    for (int rr = 0; rr < 8; ++rr) {
        int r = w * 8 + rr;
        float v0 = u.b.lgs[r][lane];
        float v1 = u.b.lgs[r][lane + 32];

        float m = fmaxf(v0, v1);
        #pragma unroll
        for (int o = 16; o > 0; o >>= 1) m = fmaxf(m, __shfl_xor_sync(0xffffffffu, m, o));
        float e0 = expf(v0 - m), e1 = expf(v1 - m);
        float s = e0 + e1;
        #pragma unroll
        for (int o = 16; o > 0; o >>= 1) s += __shfl_xor_sync(0xffffffffu, s, o);
        float inv = 1.f / s;
        float sw0 = e0 * inv, sw1 = e1 * inv;
        lb0 += sw0; lb1 += sw1;

        // local top-2 (prefer lower index on ties, matching lax.top_k)
        float bv0 = sw0, bv1 = sw1;
        int   bi0 = lane, bi1 = lane + 32;
        if (sw1 > sw0) { bv0 = sw1; bi0 = lane + 32; bv1 = sw0; bi1 = lane; }

        #pragma unroll
        for (int o = 16; o > 0; o >>= 1) {
            float ov0 = __shfl_xor_sync(0xffffffffu, bv0, o);
            int   oi0 = __shfl_xor_sync(0xffffffffu, bi0, o);
            float ov1 = __shfl_xor_sync(0xffffffffu, bv1, o);
            int   oi1 = __shfl_xor_sync(0xffffffffu, bi1, o);
            bool o0_beats_b0 = (ov0 > bv0) || (ov0 == bv0 && oi0 < bi0);
            if (o0_beats_b0) {
                bool b0_beats_o1 = (bv0 > ov1) || (bv0 == ov1 && bi0 < oi1);
                if (b0_beats_o1) { bv1 = bv0; bi1 = bi0; }
                else             { bv1 = ov1; bi1 = oi1; }
                bv0 = ov0; bi0 = oi0;
            } else {
                bool o0_beats_b1 = (ov0 > bv1) || (ov0 == bv1 && oi0 < bi1);
                if (o0_beats_b1) { bv1 = ov0; bi1 = oi0; }
            }
        }

        float rinv = 1.f / (bv0 + bv1 + 1e-8f);
        int grow = row0 + r;
        float o0 = (lane == bi0) ? bv0 * rinv : ((lane == bi1) ? bv1 * rinv : 0.f);
        float o1 = (lane + 32 == bi0) ? bv0 * rinv : ((lane + 32 == bi1) ? bv1 * rinv : 0.f);
        out[(size_t)grow * 64 + lane]      = o0;
        out[(size_t)grow * 64 + lane + 32] = o1;
        if (lane == 0) {
            out[OUT_IDX_OFF + (size_t)grow * 2 + 0] = (float)bi0;
            out[OUT_IDX_OFF + (size_t)grow * 2 + 1] = (float)bi1;
        }
    }

    // deterministic lb partials: per-warp -> per-CTA
    u.b.lbp[w][lane]      = lb0;
    u.b.lbp[w][lane + 32] = lb1;
    __syncthreads();
    if (t < N_EXP) {
        float s = 0.f;
        #pragma unroll
        for (int ww = 0; ww < 8; ++ww) s += u.b.lbp[ww][t];
        g_part[blockIdx.x * N_EXP + t] = s;
    }
}

// ---------------- final: load-balance loss ----------------
__global__ void final_kernel(float* __restrict__ out) {
    __shared__ float sh[N_EXP];
    int t = threadIdx.x;  // 64 threads
    float s = 0.f;
    for (int c = 0; c < NCTA; ++c) s += g_part[c * N_EXP + t];
    float mean = s * (1.f / ROWS);
    sh[t] = -mean * logf(mean + 1e-8f);
    __syncthreads();
    if (t == 0) {
        float acc = 0.f;
        for (int i = 0; i < N_EXP; ++i) acc += sh[i];
        out[OUT_LB_OFF] = acc;
    }
}

extern "C" void kernel_launch(void* const* d_in, const int* in_sizes, int n_in,
                              void* d_out, int out_size) {
    const float* x     = (const float*)d_in[0];
    const float* gamma = (const float*)d_in[1];
    const float* beta  = (const float*)d_in[2];
    const float* W     = (const float*)d_in[3];
    const float* b     = (const float*)d_in[4];
    float* out = (float*)d_out;

    prep_kernel<<<N_EXP, 256>>>(W, gamma, beta, b);
    main_kernel<<<NCTA, THREADS>>>(x, out);
    final_kernel<<<1, N_EXP>>>(out);
}

// round 3
// speedup vs baseline: 1.0008x; 1.0008x over previous
#include <cuda_runtime.h>
#include <math.h>

#define D_MODEL 4096
#define N_EXP   64
#define ROWS    16384          // 4 * 4096
#define LN_EPS  1e-5f
#define TM      64             // rows per CTA
#define KC      64             // k-chunk
#define NCTA    (ROWS / TM)    // 256
#define THREADS 256

// ---- device scratch (no allocations allowed) ----
__device__ float g_gw[N_EXP * D_MODEL];   // gamma ⊙ W
__device__ float g_c1[N_EXP];             // sum_k gamma_k * W[e][k]
__device__ float g_c2[N_EXP];             // sum_k beta_k * W[e][k] + b[e]
__device__ float g_part[NCTA * N_EXP];    // per-CTA softmax-weight partial sums

// Output layout (fp32, concatenated flat):
//   [0, 1048576)           sparse_w   (16384 x 64)
//   [1048576, 1081344)     indices    (16384 x 2), cast to float
//   [1081344]              lb_loss
#define OUT_IDX_OFF 1048576
#define OUT_LB_OFF  1081344

// ---------------- packed f32x2 helpers ----------------
__device__ __forceinline__ unsigned long long pack2(float lo, float hi) {
    unsigned long long r;
    asm("mov.b64 %0, {%1, %2};" : "=l"(r) : "f"(lo), "f"(hi));
    return r;
}
__device__ __forceinline__ unsigned long long fma2(unsigned long long a,
                                                   unsigned long long b,
                                                   unsigned long long c) {
    unsigned long long r;
    asm("fma.rn.f32x2 %0, %1, %2, %3;" : "=l"(r) : "l"(a), "l"(b), "l"(c));
    return r;
}
__device__ __forceinline__ void unpack2(unsigned long long v, float& lo, float& hi) {
    asm("mov.b64 {%0, %1}, %2;" : "=f"(lo), "=f"(hi) : "l"(v));
}

// ---------------- prep: gw = gamma ⊙ W, c1/c2 constants ----------------
__global__ void prep_kernel(const float* __restrict__ W,
                            const float* __restrict__ gamma,
                            const float* __restrict__ beta,
                            const float* __restrict__ b) {
    int e = blockIdx.x;
    int t = threadIdx.x;
    float a1 = 0.f, a2 = 0.f;
    const float* Wr = W + e * D_MODEL;
    for (int k = t; k < D_MODEL; k += blockDim.x) {
        float w = Wr[k];
        float gwv = gamma[k] * w;
        g_gw[e * D_MODEL + k] = gwv;
        a1 += gwv;
        a2 += beta[k] * w;
    }
    __shared__ float s1[256], s2[256];
    s1[t] = a1; s2[t] = a2;
    __syncthreads();
    for (int s = 128; s > 0; s >>= 1) {
        if (t < s) { s1[t] += s1[t + s]; s2[t] += s2[t + s]; }
        __syncthreads();
    }
    if (t == 0) { g_c1[e] = s1[0]; g_c2[e] = s2[0] + b[e]; }
}

// ---------------- main fused kernel ----------------
struct SmemA {
    float xs[KC][TM + 4];        // transposed: xs[kk][row]
    float ws[KC][N_EXP + 4];     // transposed: ws[kk][expert]
};
struct SmemB {
    float lgs[TM][N_EXP];        // logits tile
    float lbp[8][N_EXP];         // per-warp lb partials
};

__global__ __launch_bounds__(THREADS)
void main_kernel(const float* __restrict__ x, float* __restrict__ out) {
    __shared__ union { SmemA a; SmemB b; } u;
    __shared__ float srow[TM], ssrow[TM], smu[TM], srstd[TM];

    const int t    = threadIdx.x;
    const int row0 = blockIdx.x * TM;

    // loader mapping: 4 threads per row/expert-row
    const int lrow = t >> 2;         // 0..63
    const int l4   = t & 3;

    // compute mapping: 16x16 thread grid -> 4 rows x 4 experts per thread
    const int tr = t & 15;
    const int tc = t >> 4;
    const int rb = tr * 4;
    const int eb = tc * 4;

    unsigned long long accA[4], accB[4];   // accA: rows(rb,rb+1); accB: rows(rb+2,rb+3)
    #pragma unroll
    for (int i = 0; i < 4; ++i) { accA[i] = 0ull; accB[i] = 0ull; }

    float ls = 0.f, lss = 0.f;
    const float* xrow = x + (size_t)(row0 + lrow) * D_MODEL;
    const float* wrow = g_gw + (size_t)lrow * D_MODEL;

    for (int chunk = 0; chunk < D_MODEL / KC; ++chunk) {
        const int k0 = chunk * KC;
        // load X chunk (transposed into smem) + accumulate sum/sumsq
        #pragma unroll
        for (int j = 0; j < 4; ++j) {
            int col = l4 * 16 + j * 4;
            float4 v = *(const float4*)(xrow + k0 + col);
            u.a.xs[col + 0][lrow] = v.x;
            u.a.xs[col + 1][lrow] = v.y;
            u.a.xs[col + 2][lrow] = v.z;
            u.a.xs[col + 3][lrow] = v.w;
            ls  += v.x + v.y + v.z + v.w;
            lss += v.x * v.x + v.y * v.y + v.z * v.z + v.w * v.w;
        }
        // load gW chunk (transposed)
        #pragma unroll
        for (int j = 0; j < 4; ++j) {
            int col = l4 * 16 + j * 4;
            float4 v = *(const float4*)(wrow + k0 + col);
            u.a.ws[col + 0][lrow] = v.x;
            u.a.ws[col + 1][lrow] = v.y;
            u.a.ws[col + 2][lrow] = v.z;
            u.a.ws[col + 3][lrow] = v.w;
        }
        __syncthreads();

        #pragma unroll 8
        for (int kk = 0; kk < KC; ++kk) {
            float4 xv = *(const float4*)&u.a.xs[kk][rb];
            float4 wv = *(const float4*)&u.a.ws[kk][eb];
            unsigned long long xA = pack2(xv.x, xv.y);
            unsigned long long xB = pack2(xv.z, xv.w);
            unsigned long long w0 = pack2(wv.x, wv.x);
            unsigned long long w1 = pack2(wv.y, wv.y);
            unsigned long long w2 = pack2(wv.z, wv.z);
            unsigned long long w3 = pack2(wv.w, wv.w);
            accA[0] = fma2(xA, w0, accA[0]);  accB[0] = fma2(xB, w0, accB[0]);
            accA[1] = fma2(xA, w1, accA[1]);  accB[1] = fma2(xB, w1, accB[1]);
            accA[2] = fma2(xA, w2, accA[2]);  accB[2] = fma2(xB, w2, accB[2]);
            accA[3] = fma2(xA, w3, accA[3]);  accB[3] = fma2(xB, w3, accB[3]);
        }
        __syncthreads();
    }

    // reduce sum/sumsq within each loader quad (4 consecutive lanes)
    ls  += __shfl_xor_sync(0xffffffffu, ls, 1);
    ls  += __shfl_xor_sync(0xffffffffu, ls, 2);
    lss += __shfl_xor_sync(0xffffffffu, lss, 1);
    lss += __shfl_xor_sync(0xffffffffu, lss, 2);
    if (l4 == 0) { srow[lrow] = ls; ssrow[lrow] = lss; }
    __syncthreads();

    if (t < TM) {
        float mu  = srow[t] * (1.f / D_MODEL);
        float var = ssrow[t] * (1.f / D_MODEL) - mu * mu;
        smu[t]   = mu;
        srstd[t] = rsqrtf(var + LN_EPS);
    }
    __syncthreads();

    // logits into shared (union flips to SmemB: all SmemA reads are behind syncs)
    {
        float mu0 = smu[rb + 0], mu1 = smu[rb + 1], mu2 = smu[rb + 2], mu3 = smu[rb + 3];
        float rs0 = srstd[rb + 0], rs1 = srstd[rb + 1], rs2 = srstd[rb + 2], rs3 = srstd[rb + 3];
        #pragma unroll
        for (int i = 0; i < 4; ++i) {
            float c1 = g_c1[eb + i];
            float c2 = g_c2[eb + i];
            float a0, a1, a2, a3;
            unpack2(accA[i], a0, a1);
            unpack2(accB[i], a2, a3);
            u.b.lgs[rb + 0][eb + i] = rs0 * (a0 - mu0 * c1) + c2;
            u.b.lgs[rb + 1][eb + i] = rs1 * (a1 - mu1 * c1) + c2;
            u.b.lgs[rb + 2][eb + i] = rs2 * (a2 - mu2 * c1) + c2;
            u.b.lgs[rb + 3][eb + i] = rs3 * (a3 - mu3 * c1) + c2;
        }
    }
    __syncthreads();

    // softmax + top-2 + scatter + renorm : one warp handles 8 rows
    const int w    = t >> 5;
    const int lane = t & 31;
    float lb0 = 0.f, lb1 = 0.f;

    for (int rr = 0; rr < 8; ++rr) {
        int r = w * 8 + rr;
        float v0 = u.b.lgs[r][lane];
        float v1 = u.b.lgs[r][lane + 32];

        float m = fmaxf(v0, v1);
        #pragma unroll
        for (int o = 16; o > 0; o >>= 1) m = fmaxf(m, __shfl_xor_sync(0xffffffffu, m, o));
        float e0 = expf(v0 - m), e1 = expf(v1 - m);
        float s = e0 + e1;
        #pragma unroll
        for (int o = 16; o > 0; o >>= 1) s += __shfl_xor_sync(0xffffffffu, s, o);
        float inv = 1.f / s;
        float sw0 = e0 * inv, sw1 = e1 * inv;
        lb0 += sw0; lb1 += sw1;

        // local top-2 (prefer lower index on ties, matching lax.top_k)
        float bv0 = sw0, bv1 = sw1;
        int   bi0 = lane, bi1 = lane + 32;
        if (sw1 > sw0) { bv0 = sw1; bi0 = lane + 32; bv1 = sw0; bi1 = lane; }

        #pragma unroll
        for (int o = 16; o > 0; o >>= 1) {
            float ov0 = __shfl_xor_sync(0xffffffffu, bv0, o);
            int   oi0 = __shfl_xor_sync(0xffffffffu, bi0, o);
            float ov1 = __shfl_xor_sync(0xffffffffu, bv1, o);
            int   oi1 = __shfl_xor_sync(0xffffffffu, bi1, o);
            bool o0_beats_b0 = (ov0 > bv0) || (ov0 == bv0 && oi0 < bi0);
            if (o0_beats_b0) {
                bool b0_beats_o1 = (bv0 > ov1) || (bv0 == ov1 && bi0 < oi1);
                if (b0_beats_o1) { bv1 = bv0; bi1 = bi0; }
                else             { bv1 = ov1; bi1 = oi1; }
                bv0 = ov0; bi0 = oi0;
            } else {
                bool o0_beats_b1 = (ov0 > bv1) || (ov0 == bv1 && oi0 < bi1);
                if (o0_beats_b1) { bv1 = ov0; bi1 = oi0; }
            }
        }

        float rinv = 1.f / (bv0 + bv1 + 1e-8f);
        int grow = row0 + r;
        float o0 = (lane == bi0) ? bv0 * rinv : ((lane == bi1) ? bv1 * rinv : 0.f);
        float o1 = (lane + 32 == bi0) ? bv0 * rinv : ((lane + 32 == bi1) ? bv1 * rinv : 0.f);
        out[(size_t)grow * 64 + lane]      = o0;
        out[(size_t)grow * 64 + lane + 32] = o1;
        if (lane == 0) {
            out[OUT_IDX_OFF + (size_t)grow * 2 + 0] = (float)bi0;
            out[OUT_IDX_OFF + (size_t)grow * 2 + 1] = (float)bi1;
        }
    }

    // deterministic lb partials: per-warp -> per-CTA
    u.b.lbp[w][lane]      = lb0;
    u.b.lbp[w][lane + 32] = lb1;
    __syncthreads();
    if (t < N_EXP) {
        float s = 0.f;
        #pragma unroll
        for (int ww = 0; ww < 8; ++ww) s += u.b.lbp[ww][t];
        g_part[blockIdx.x * N_EXP + t] = s;
    }
}

// ---------------- final: load-balance loss ----------------
__global__ void final_kernel(float* __restrict__ out) {
    __shared__ float sh[N_EXP];
    int t = threadIdx.x;  // 64 threads
    float s = 0.f;
    for (int c = 0; c < NCTA; ++c) s += g_part[c * N_EXP + t];
    float mean = s * (1.f / ROWS);
    sh[t] = -mean * logf(mean + 1e-8f);
    __syncthreads();
    if (t == 0) {
        float acc = 0.f;
        for (int i = 0; i < N_EXP; ++i) acc += sh[i];
        out[OUT_LB_OFF] = acc;
    }
}

extern "C" void kernel_launch(void* const* d_in, const int* in_sizes, int n_in,
                              void* d_out, int out_size) {
    const float* x     = (const float*)d_in[0];
    const float* gamma = (const float*)d_in[1];
    const float* beta  = (const float*)d_in[2];
    const float* W     = (const float*)d_in[3];
    const float* b     = (const float*)d_in[4];
    float* out = (float*)d_out;

    prep_kernel<<<N_EXP, 256>>>(W, gamma, beta, b);
    main_kernel<<<NCTA, THREADS>>>(x, out);
    final_kernel<<<1, N_EXP>>>(out);
}

// round 5
// speedup vs baseline: 2.1110x; 2.1093x over previous
#include <cuda_runtime.h>
#include <cuda_fp16.h>
#include <math.h>
#include <stdint.h>

#define D_MODEL 4096
#define N_EXP   64
#define ROWS    16384          // 4 * 4096
#define LN_EPS  1e-5f
#define TM      128            // rows per CTA
#define NSTAGE  64             // K chunks of 64
#define NCTA    (ROWS / TM)    // 128
#define THREADS 256

// Output layout (fp32 flat): sparse_w[16384*64], indices[16384*2] as float, lb_loss
#define OUT_IDX_OFF 1048576
#define OUT_LB_OFF  1081344

// ---- dynamic smem layout ----
// A tiles: 128 rows x 72 halves (144B stride, conflict-free frag loads), 2 parts
// B tiles: 64 rows  x 72 halves, 2 parts
#define A_STR 144
#define B_STR 144
#define AH_O  0
#define AM_O  18432
#define BH_O  36864
#define BM_O  46080
#define BUFB  55296
#define EXT   (2 * BUFB)          // 110592
#define MU_O  (EXT)
#define RS_O  (EXT + 512)
#define C1_O  (EXT + 1024)
#define C2_O  (EXT + 1280)
#define SMEM_REQ (EXT + 1536)     // 112128 bytes

// ---- device scratch ----
__device__ __align__(16) __half g_wh[N_EXP * D_MODEL];  // high fp16 part of gamma*W
__device__ __align__(16) __half g_wm[N_EXP * D_MODEL];  // mid  fp16 part
__device__ float g_c1[N_EXP];
__device__ float g_c2[N_EXP];
__device__ float g_part[NCTA * N_EXP];

__device__ __forceinline__ uint32_t pack_half2(__half a, __half b) {
    __half2 h = __halves2half2(a, b);
    return *reinterpret_cast<uint32_t*>(&h);
}

__device__ __forceinline__ void mma16816(float* c, const uint32_t* a, const uint32_t* b) {
    asm volatile(
        "mma.sync.aligned.m16n8k16.row.col.f32.f16.f16.f32 "
        "{%0,%1,%2,%3}, {%4,%5,%6,%7}, {%8,%9}, {%0,%1,%2,%3};"
        : "+f"(c[0]), "+f"(c[1]), "+f"(c[2]), "+f"(c[3])
        : "r"(a[0]), "r"(a[1]), "r"(a[2]), "r"(a[3]), "r"(b[0]), "r"(b[1]));
}

// ================= prep: split gamma*W into fp16 h/m parts + c1/c2 =================
__global__ void prep_kernel(const float* __restrict__ W,
                            const float* __restrict__ gamma,
                            const float* __restrict__ beta,
                            const float* __restrict__ b) {
    int e = blockIdx.x;
    int t = threadIdx.x;
    float a1 = 0.f, a2 = 0.f;
    #pragma unroll 4
    for (int i = 0; i < 16; ++i) {
        int k = i * 256 + t;
        float w  = W[e * D_MODEL + k];
        float gw = gamma[k] * w;
        a1 += gw;
        a2 += beta[k] * w;
        __half h = __float2half_rn(gw);
        float  r = gw - __half2float(h);
        __half m = __float2half_rn(r);
        g_wh[e * D_MODEL + k] = h;
        g_wm[e * D_MODEL + k] = m;
    }
    __shared__ float s1[256], s2[256];
    s1[t] = a1; s2[t] = a2;
    __syncthreads();
    for (int s = 128; s > 0; s >>= 1) {
        if (t < s) { s1[t] += s1[t + s]; s2[t] += s2[t + s]; }
        __syncthreads();
    }
    if (t == 0) { g_c1[e] = s1[0]; g_c2[e] = s2[0] + b[e]; }
}

// ================= main fused kernel =================
extern __shared__ char smem_dyn[];

__global__ __launch_bounds__(THREADS, 1)
void main_kernel(const float* __restrict__ x, float* __restrict__ out) {
    char* smb = smem_dyn;
    const int t    = threadIdx.x;
    const int lane = t & 31;
    const int wid  = t >> 5;
    const int wm   = wid & 3;       // M block (32 rows)
    const int wn   = wid >> 2;      // N block (32 cols)
    const int row0 = blockIdx.x * TM;

    if (t < 64) {
        ((float*)(smb + C1_O))[t] = g_c1[t];
        ((float*)(smb + C2_O))[t] = g_c2[t];
    }

    // producer mapping: 2 threads per row (32 cols each); B copier: rows brow, brow+32
    const int pr = t >> 1, ph = t & 1;
    const int brow = t >> 3, bc = t & 7;
    const float4* xp  = (const float4*)(x + (size_t)(row0 + pr) * D_MODEL + ph * 32);
    const uint4*  bhp = (const uint4*)g_wh;
    const uint4*  bmp = (const uint4*)g_wm;

    float acc[2][4][4];
    #pragma unroll
    for (int mi = 0; mi < 2; ++mi)
        #pragma unroll
        for (int ni = 0; ni < 4; ++ni)
            #pragma unroll
            for (int q = 0; q < 4; ++q) acc[mi][ni][q] = 0.f;

    float ls = 0.f, lss = 0.f;

    // fragment-load byte offsets (within a buffer)
    const int a_off = (wm * 32 + (lane >> 2)) * A_STR + (lane & 3) * 4;
    const int b_off = (wn * 32 + (lane >> 2)) * B_STR + (lane & 3) * 4;

    // preload stage 0
    float4 cx[8];
    uint4  cbh[2], cbm[2];
    #pragma unroll
    for (int j = 0; j < 8; ++j) cx[j] = xp[j];
    cbh[0] = bhp[(size_t)brow * 512 + bc];
    cbh[1] = bhp[(size_t)(brow + 32) * 512 + bc];
    cbm[0] = bmp[(size_t)brow * 512 + bc];
    cbm[1] = bmp[(size_t)(brow + 32) * 512 + bc];

    for (int s = 0; s < NSTAGE; ++s) {
        char* bb = smb + (s & 1) * BUFB;

        // ---- STS B (pre-split fp16) ----
        *(uint4*)(bb + BH_O + brow * B_STR + bc * 16)        = cbh[0];
        *(uint4*)(bb + BH_O + (brow + 32) * B_STR + bc * 16) = cbh[1];
        *(uint4*)(bb + BM_O + brow * B_STR + bc * 16)        = cbm[0];
        *(uint4*)(bb + BM_O + (brow + 32) * B_STR + bc * 16) = cbm[1];

        // ---- split x -> fp16 h/m, STS A, accumulate LN stats ----
        #pragma unroll
        for (int g = 0; g < 4; ++g) {
            float4 a = cx[2 * g], c = cx[2 * g + 1];
            float f[8] = {a.x, a.y, a.z, a.w, c.x, c.y, c.z, c.w};
            uint32_t hp[4], mp[4];
            #pragma unroll
            for (int i = 0; i < 4; ++i) {
                float f0 = f[2 * i], f1 = f[2 * i + 1];
                __half h0 = __float2half_rn(f0), h1 = __float2half_rn(f1);
                float  r0 = f0 - __half2float(h0), r1 = f1 - __half2float(h1);
                __half m0 = __float2half_rn(r0), m1 = __float2half_rn(r1);
                hp[i] = pack_half2(h0, h1);
                mp[i] = pack_half2(m0, m1);
                ls  += f0 + f1;
                lss  = fmaf(f0, f0, fmaf(f1, f1, lss));
            }
            uint32_t ab = pr * A_STR + ph * 64 + g * 16;
            *(uint4*)(bb + AH_O + ab) = make_uint4(hp[0], hp[1], hp[2], hp[3]);
            *(uint4*)(bb + AM_O + ab) = make_uint4(mp[0], mp[1], mp[2], mp[3]);
        }

        // ---- prefetch next stage into regs (overlaps with compute below) ----
        if (s + 1 < NSTAGE) {
            #pragma unroll
            for (int j = 0; j < 8; ++j) cx[j] = xp[(s + 1) * 16 + j];
            cbh[0] = bhp[(size_t)brow * 512 + (s + 1) * 8 + bc];
            cbh[1] = bhp[(size_t)(brow + 32) * 512 + (s + 1) * 8 + bc];
            cbm[0] = bmp[(size_t)brow * 512 + (s + 1) * 8 + bc];
            cbm[1] = bmp[(size_t)(brow + 32) * 512 + (s + 1) * 8 + bc];
        }

        __syncthreads();

        // ---- compute: 4 x k16 steps, 3 products each ----
        #pragma unroll
        for (int kk = 0; kk < 4; ++kk) {
            const int kb = kk * 32;
            uint32_t ah[2][4], am[2][4];
            #pragma unroll
            for (int mi = 0; mi < 2; ++mi) {
                const char* pa = bb + AH_O + a_off + mi * 2304 + kb;
                ah[mi][0] = *(const uint32_t*)(pa);
                ah[mi][1] = *(const uint32_t*)(pa + 1152);
                ah[mi][2] = *(const uint32_t*)(pa + 16);
                ah[mi][3] = *(const uint32_t*)(pa + 1168);
                const char* pm = pa + (AM_O - AH_O);
                am[mi][0] = *(const uint32_t*)(pm);
                am[mi][1] = *(const uint32_t*)(pm + 1152);
                am[mi][2] = *(const uint32_t*)(pm + 16);
                am[mi][3] = *(const uint32_t*)(pm + 1168);
            }
            uint32_t bh[4][2], bm[4][2];
            #pragma unroll
            for (int ni = 0; ni < 4; ++ni) {
                const char* pb = bb + BH_O + b_off + ni * 8 * B_STR + kb;
                bh[ni][0] = *(const uint32_t*)(pb);
                bh[ni][1] = *(const uint32_t*)(pb + 16);
                const char* pq = pb + (BM_O - BH_O);
                bm[ni][0] = *(const uint32_t*)(pq);
                bm[ni][1] = *(const uint32_t*)(pq + 16);
            }
            #pragma unroll
            for (int mi = 0; mi < 2; ++mi)
                #pragma unroll
                for (int ni = 0; ni < 4; ++ni) {
                    mma16816(acc[mi][ni], ah[mi], bh[ni]);
                    mma16816(acc[mi][ni], ah[mi], bm[ni]);
                    mma16816(acc[mi][ni], am[mi], bh[ni]);
                }
        }
    }

    // ---- LN stats ----
    ls  += __shfl_xor_sync(0xffffffffu, ls, 1);
    lss += __shfl_xor_sync(0xffffffffu, lss, 1);
    if (ph == 0) {
        float mu  = ls * (1.f / D_MODEL);
        float var = lss * (1.f / D_MODEL) - mu * mu;
        ((float*)(smb + MU_O))[pr] = mu;
        ((float*)(smb + RS_O))[pr] = rsqrtf(var + LN_EPS);
    }
    __syncthreads();

    // ---- dump raw dot products to smem logits tile [128][68] (reuses buf0) ----
    float* lgs = (float*)smb;
    #pragma unroll
    for (int mi = 0; mi < 2; ++mi)
        #pragma unroll
        for (int ni = 0; ni < 4; ++ni) {
            int row = wm * 32 + mi * 16 + (lane >> 2);
            int col = wn * 32 + ni * 8 + (lane & 3) * 2;
            lgs[row * 68 + col]           = acc[mi][ni][0];
            lgs[row * 68 + col + 1]       = acc[mi][ni][1];
            lgs[(row + 8) * 68 + col]     = acc[mi][ni][2];
            lgs[(row + 8) * 68 + col + 1] = acc[mi][ni][3];
        }
    __syncthreads();

    // ---- per-row epilogue: LN correction, top-2 on logits, softmax, scatter ----
    if (t < TM) {
        const float mu = ((float*)(smb + MU_O))[t];
        const float rs = ((float*)(smb + RS_O))[t];
        const float* c1 = (const float*)(smb + C1_O);
        const float* c2 = (const float*)(smb + C2_O);
        float* lrow = lgs + t * 68;

        float mx = -1e30f, v0 = -1e30f, v1 = -1e30f;
        int i0 = 0, i1 = 0;
        #pragma unroll 8
        for (int e = 0; e < 64; ++e) {
            float v = fmaf(-mu, c1[e], lrow[e]) * rs + c2[e];
            lrow[e] = v;
            mx = fmaxf(mx, v);
            if (v > v0)      { v1 = v0; i1 = i0; v0 = v; i0 = e; }
            else if (v > v1) { v1 = v; i1 = e; }
        }
        float sum = 0.f;
        #pragma unroll 8
        for (int e = 0; e < 64; ++e) {
            float ev = __expf(lrow[e] - mx);
            lrow[e] = ev;
            sum += ev;
        }
        float inv = 1.f / sum;
        float sw0 = __expf(v0 - mx) * inv;
        float sw1 = __expf(v1 - mx) * inv;
        float rn  = 1.f / (sw0 + sw1 + 1e-8f);
        float o0 = sw0 * rn, o1 = sw1 * rn;

        int grow = row0 + t;
        float* orow = out + (size_t)grow * 64;
        #pragma unroll
        for (int e = 0; e < 64; e += 4) {
            float w0 = lrow[e + 0] * inv;
            float w1 = lrow[e + 1] * inv;
            float w2 = lrow[e + 2] * inv;
            float w3 = lrow[e + 3] * inv;
            lrow[e + 0] = w0; lrow[e + 1] = w1;
            lrow[e + 2] = w2; lrow[e + 3] = w3;
            float4 o;
            o.x = (e + 0 == i0) ? o0 : ((e + 0 == i1) ? o1 : 0.f);
            o.y = (e + 1 == i0) ? o0 : ((e + 1 == i1) ? o1 : 0.f);
            o.z = (e + 2 == i0) ? o0 : ((e + 2 == i1) ? o1 : 0.f);
            o.w = (e + 3 == i0) ? o0 : ((e + 3 == i1) ? o1 : 0.f);
            *(float4*)(orow + e) = o;
        }
        out[OUT_IDX_OFF + (size_t)grow * 2 + 0] = (float)i0;
        out[OUT_IDX_OFF + (size_t)grow * 2 + 1] = (float)i1;
    }
    __syncthreads();

    // ---- deterministic per-CTA lb partials ----
    if (t < N_EXP) {
        float s = 0.f;
        #pragma unroll 8
        for (int r = 0; r < TM; ++r) s += lgs[r * 68 + t];
        g_part[blockIdx.x * N_EXP + t] = s;
    }
}

// ================= final: load-balance loss =================
__global__ void final_kernel(float* __restrict__ out) {
    __shared__ float sh[N_EXP];
    int t = threadIdx.x;  // 64 threads
    float s = 0.f;
    for (int c = 0; c < NCTA; ++c) s += g_part[c * N_EXP + t];
    float mean = s * (1.f / ROWS);
    sh[t] = -mean * logf(mean + 1e-8f);
    __syncthreads();
    if (t == 0) {
        float acc = 0.f;
        for (int i = 0; i < N_EXP; ++i) acc += sh[i];
        out[OUT_LB_OFF] = acc;
    }
}

extern "C" void kernel_launch(void* const* d_in, const int* in_sizes, int n_in,
                              void* d_out, int out_size) {
    const float* x     = (const float*)d_in[0];
    const float* gamma = (const float*)d_in[1];
    const float* beta  = (const float*)d_in[2];
    const float* W     = (const float*)d_in[3];
    const float* b     = (const float*)d_in[4];
    float* out = (float*)d_out;

    cudaFuncSetAttribute(main_kernel, cudaFuncAttributeMaxDynamicSharedMemorySize, SMEM_REQ);

    prep_kernel<<<N_EXP, 256>>>(W, gamma, beta, b);
    main_kernel<<<NCTA, THREADS, SMEM_REQ>>>(x, out);
    final_kernel<<<1, N_EXP>>>(out);
}

// round 6
// speedup vs baseline: 2.5755x; 1.2200x over previous
#include <cuda_runtime.h>
#include <cuda_fp16.h>
#include <math.h>
#include <stdint.h>

#define D_MODEL 4096
#define N_EXP   64
#define ROWS    16384          // 4 * 4096
#define LN_EPS  1e-5f
#define TM      128            // rows per CTA
#define NSTAGE  64             // K chunks of 64
#define NCTA    (ROWS / TM)    // 128
#define THREADS 256

// Output layout (fp32 flat): sparse_w[16384*64], indices[16384*2] as float, lb_loss
#define OUT_IDX_OFF 1048576
#define OUT_LB_OFF  1081344

// ---- dynamic smem layout ----
// A tiles: 128 rows x 72 halves (144B stride), parts h/m ; B tiles: 64 rows x 72 halves
#define A_STR 144
#define B_STR 144
#define AH_O  0
#define AM_O  18432
#define BH_O  36864
#define BM_O  46080
#define BUFB  55296
#define EXT   (2 * BUFB)          // 110592
#define MU_O  (EXT)
#define RS_O  (EXT + 512)
#define C1_O  (EXT + 1024)
#define C2_O  (EXT + 1280)
#define SMEM_REQ (EXT + 1536)     // 112128 bytes

// ---- device scratch ----
__device__ __align__(16) __half g_wh[N_EXP * D_MODEL];  // high fp16 part of gamma*W
__device__ __align__(16) __half g_wm[N_EXP * D_MODEL];  // mid  fp16 part
__device__ float g_c1[N_EXP];
__device__ float g_c2[N_EXP];
__device__ float g_part[NCTA * N_EXP];

// ================= PTX helpers =================
__device__ __forceinline__ uint32_t smem_u32(const void* p) {
    uint32_t a;
    asm("{ .reg .u64 t; cvta.to.shared.u64 t, %1; cvt.u32.u64 %0, t; }" : "=r"(a) : "l"(p));
    return a;
}
__device__ __forceinline__ void ldsm4(uint32_t* r, uint32_t addr) {
    asm volatile("ldmatrix.sync.aligned.m8n8.x4.shared.b16 {%0,%1,%2,%3}, [%4];"
                 : "=r"(r[0]), "=r"(r[1]), "=r"(r[2]), "=r"(r[3]) : "r"(addr));
}
__device__ __forceinline__ void mma16816(float* c, const uint32_t* a, const uint32_t* b) {
    asm volatile(
        "mma.sync.aligned.m16n8k16.row.col.f32.f16.f16.f32 "
        "{%0,%1,%2,%3}, {%4,%5,%6,%7}, {%8,%9}, {%0,%1,%2,%3};"
        : "+f"(c[0]), "+f"(c[1]), "+f"(c[2]), "+f"(c[3])
        : "r"(a[0]), "r"(a[1]), "r"(a[2]), "r"(a[3]), "r"(b[0]), "r"(b[1]));
}
__device__ __forceinline__ uint32_t cvt_h2(float lo, float hi) {
    uint32_t r;
    asm("cvt.rn.f16x2.f32 %0, %1, %2;" : "=r"(r) : "f"(hi), "f"(lo));
    return r;
}

// ================= prep: split gamma*W into fp16 h/m parts + c1/c2 =================
__global__ void prep_kernel(const float* __restrict__ W,
                            const float* __restrict__ gamma,
                            const float* __restrict__ beta,
                            const float* __restrict__ b) {
    int e = blockIdx.x;
    int t = threadIdx.x;
    float a1 = 0.f, a2 = 0.f;
    #pragma unroll 4
    for (int i = 0; i < 16; ++i) {
        int k = i * 256 + t;
        float w  = W[e * D_MODEL + k];
        float gw = gamma[k] * w;
        a1 += gw;
        a2 += beta[k] * w;
        __half h = __float2half_rn(gw);
        float  r = gw - __half2float(h);
        __half m = __float2half_rn(r);
        g_wh[e * D_MODEL + k] = h;
        g_wm[e * D_MODEL + k] = m;
    }
    __shared__ float s1[256], s2[256];
    s1[t] = a1; s2[t] = a2;
    __syncthreads();
    for (int s = 128; s > 0; s >>= 1) {
        if (t < s) { s1[t] += s1[t + s]; s2[t] += s2[t + s]; }
        __syncthreads();
    }
    if (t == 0) { g_c1[e] = s1[0]; g_c2[e] = s2[0] + b[e]; }
}

// ================= main fused kernel =================
extern __shared__ char smem_dyn[];

__global__ __launch_bounds__(THREADS, 1)
void main_kernel(const float* __restrict__ x, float* __restrict__ out) {
    char* smb = smem_dyn;
    const uint32_t sbase = smem_u32(smb);
    const int t    = threadIdx.x;
    const int lane = t & 31;
    const int wid  = t >> 5;
    const int wm   = wid & 3;       // M block (32 rows)
    const int wn   = wid >> 2;      // N block (32 cols)
    const int row0 = blockIdx.x * TM;

    if (t < 64) {
        ((float*)(smb + C1_O))[t] = g_c1[t];
        ((float*)(smb + C2_O))[t] = g_c2[t];
    }

    // producer mapping: 2 threads per row (32 cols each); B copier rows brow, brow+32
    const int pr = t >> 1, ph = t & 1;
    const int brow = t >> 3, bc = t & 7;
    const float4* xp  = (const float4*)(x + (size_t)(row0 + pr) * D_MODEL + ph * 32);
    const uint4*  bhp = (const uint4*)g_wh;
    const uint4*  bmp = (const uint4*)g_wm;

    // ldmatrix lane offsets
    const uint32_t aoff = (uint32_t)((wm * 32 + (lane & 15)) * A_STR + (lane >> 4) * 16);
    const uint32_t boff = (uint32_t)((wn * 32 + ((lane >> 4) & 1) * 8 + (lane & 7)) * B_STR
                                     + ((lane >> 3) & 1) * 16);
    const uint32_t a_sts = (uint32_t)(pr * A_STR + ph * 64);
    const uint32_t b_sts_lo = (uint32_t)(brow * B_STR + bc * 16);
    const uint32_t b_sts_hi = (uint32_t)((brow + 32) * B_STR + bc * 16);

    float acc[2][4][4];
    #pragma unroll
    for (int mi = 0; mi < 2; ++mi)
        #pragma unroll
        for (int ni = 0; ni < 4; ++ni)
            #pragma unroll
            for (int q = 0; q < 4; ++q) acc[mi][ni][q] = 0.f;

    float ls = 0.f, lss = 0.f;

    float4 cx[8];
    uint4  cbh[2], cbm[2];

    // ---- prologue: load stage 0, split+store into buf0, prefetch stage 1 ----
    #pragma unroll
    for (int j = 0; j < 8; ++j) cx[j] = xp[j];
    cbh[0] = bhp[(size_t)brow * 512 + bc];
    cbh[1] = bhp[(size_t)(brow + 32) * 512 + bc];
    cbm[0] = bmp[(size_t)brow * 512 + bc];
    cbm[1] = bmp[(size_t)(brow + 32) * 512 + bc];

    {
        char* bb = smb;   // buf0
        *(uint4*)(bb + BH_O + b_sts_lo) = cbh[0];
        *(uint4*)(bb + BH_O + b_sts_hi) = cbh[1];
        *(uint4*)(bb + BM_O + b_sts_lo) = cbm[0];
        *(uint4*)(bb + BM_O + b_sts_hi) = cbm[1];
        #pragma unroll
        for (int g = 0; g < 4; ++g) {
            float4 a = cx[2 * g], c = cx[2 * g + 1];
            float f[8] = {a.x, a.y, a.z, a.w, c.x, c.y, c.z, c.w};
            uint32_t hp[4], mp[4];
            #pragma unroll
            for (int i = 0; i < 4; ++i) {
                float f0 = f[2 * i], f1 = f[2 * i + 1];
                uint32_t h2 = cvt_h2(f0, f1);
                __half2 hh = *(__half2*)&h2;
                float2 bk = __half22float2(hh);
                mp[i] = cvt_h2(f0 - bk.x, f1 - bk.y);
                hp[i] = h2;
                ls  += f0 + f1;
                lss  = fmaf(f0, f0, fmaf(f1, f1, lss));
            }
            *(uint4*)(bb + AH_O + a_sts + g * 16) = make_uint4(hp[0], hp[1], hp[2], hp[3]);
            *(uint4*)(bb + AM_O + a_sts + g * 16) = make_uint4(mp[0], mp[1], mp[2], mp[3]);
        }
        // prefetch stage 1
        #pragma unroll
        for (int j = 0; j < 8; ++j) cx[j] = xp[16 + j];
        cbh[0] = bhp[(size_t)brow * 512 + 8 + bc];
        cbh[1] = bhp[(size_t)(brow + 32) * 512 + 8 + bc];
        cbm[0] = bmp[(size_t)brow * 512 + 8 + bc];
        cbm[1] = bmp[(size_t)(brow + 32) * 512 + 8 + bc];
    }
    __syncthreads();

    // ---- main loop: MMA(stage s) || split+STS(stage s+1) || LDG(stage s+2) ----
    for (int s = 0; s < NSTAGE; ++s) {
        const uint32_t rb = sbase + (uint32_t)((s & 1) * BUFB);
        char* wbuf = smb + ((s + 1) & 1) * BUFB;

        const uint32_t abh = rb + AH_O + aoff;
        const uint32_t abm = rb + AM_O + aoff;
        const uint32_t bbh = rb + BH_O + boff;
        const uint32_t bbm = rb + BM_O + boff;

        // MMA section first (LDS before any STS in program order)
        #pragma unroll
        for (int kk = 0; kk < 4; ++kk) {
            const uint32_t kb = kk * 32;
            uint32_t ah0[4], ah1[4], am0[4], am1[4];
            uint32_t bh01[4], bh23[4], bm01[4], bm23[4];
            ldsm4(ah0, abh + kb);
            ldsm4(ah1, abh + 2304 + kb);
            ldsm4(am0, abm + kb);
            ldsm4(am1, abm + 2304 + kb);
            ldsm4(bh01, bbh + kb);
            ldsm4(bh23, bbh + 2304 + kb);
            ldsm4(bm01, bbm + kb);
            ldsm4(bm23, bbm + 2304 + kb);
            const uint32_t* bhv[4] = {bh01, bh01 + 2, bh23, bh23 + 2};
            const uint32_t* bmv[4] = {bm01, bm01 + 2, bm23, bm23 + 2};
            #pragma unroll
            for (int ni = 0; ni < 4; ++ni) {
                mma16816(acc[0][ni], ah0, bhv[ni]);
                mma16816(acc[1][ni], ah1, bhv[ni]);
                mma16816(acc[0][ni], ah0, bmv[ni]);
                mma16816(acc[1][ni], ah1, bmv[ni]);
                mma16816(acc[0][ni], am0, bhv[ni]);
                mma16816(acc[1][ni], am1, bhv[ni]);
            }
        }

        // split + STS for stage s+1 into the other buffer
        if (s + 1 < NSTAGE) {
            *(uint4*)(wbuf + BH_O + b_sts_lo) = cbh[0];
            *(uint4*)(wbuf + BH_O + b_sts_hi) = cbh[1];
            *(uint4*)(wbuf + BM_O + b_sts_lo) = cbm[0];
            *(uint4*)(wbuf + BM_O + b_sts_hi) = cbm[1];
            #pragma unroll
            for (int g = 0; g < 4; ++g) {
                float4 a = cx[2 * g], c = cx[2 * g + 1];
                float f[8] = {a.x, a.y, a.z, a.w, c.x, c.y, c.z, c.w};
                uint32_t hp[4], mp[4];
                #pragma unroll
                for (int i = 0; i < 4; ++i) {
                    float f0 = f[2 * i], f1 = f[2 * i + 1];
                    uint32_t h2 = cvt_h2(f0, f1);
                    __half2 hh = *(__half2*)&h2;
                    float2 bk = __half22float2(hh);
                    mp[i] = cvt_h2(f0 - bk.x, f1 - bk.y);
                    hp[i] = h2;
                    ls  += f0 + f1;
                    lss  = fmaf(f0, f0, fmaf(f1, f1, lss));
                }
                *(uint4*)(wbuf + AH_O + a_sts + g * 16) = make_uint4(hp[0], hp[1], hp[2], hp[3]);
                *(uint4*)(wbuf + AM_O + a_sts + g * 16) = make_uint4(mp[0], mp[1], mp[2], mp[3]);
            }
        }

        // LDG prefetch stage s+2
        if (s + 2 < NSTAGE) {
            #pragma unroll
            for (int j = 0; j < 8; ++j) cx[j] = xp[(s + 2) * 16 + j];
            cbh[0] = bhp[(size_t)brow * 512 + (s + 2) * 8 + bc];
            cbh[1] = bhp[(size_t)(brow + 32) * 512 + (s + 2) * 8 + bc];
            cbm[0] = bmp[(size_t)brow * 512 + (s + 2) * 8 + bc];
            cbm[1] = bmp[(size_t)(brow + 32) * 512 + (s + 2) * 8 + bc];
        }

        __syncthreads();
    }

    // ---- LN stats ----
    ls  += __shfl_xor_sync(0xffffffffu, ls, 1);
    lss += __shfl_xor_sync(0xffffffffu, lss, 1);
    if (ph == 0) {
        float mu  = ls * (1.f / D_MODEL);
        float var = lss * (1.f / D_MODEL) - mu * mu;
        ((float*)(smb + MU_O))[pr] = mu;
        ((float*)(smb + RS_O))[pr] = rsqrtf(var + LN_EPS);
    }
    __syncthreads();

    // ---- dump raw dot products to smem logits tile [128][68] (reuses buf0) ----
    float* lgs = (float*)smb;
    #pragma unroll
    for (int mi = 0; mi < 2; ++mi)
        #pragma unroll
        for (int ni = 0; ni < 4; ++ni) {
            int row = wm * 32 + mi * 16 + (lane >> 2);
            int col = wn * 32 + ni * 8 + (lane & 3) * 2;
            lgs[row * 68 + col]           = acc[mi][ni][0];
            lgs[row * 68 + col + 1]       = acc[mi][ni][1];
            lgs[(row + 8) * 68 + col]     = acc[mi][ni][2];
            lgs[(row + 8) * 68 + col + 1] = acc[mi][ni][3];
        }
    __syncthreads();

    // ---- per-row epilogue: LN correction, top-2 on logits, softmax, scatter ----
    if (t < TM) {
        const float mu = ((float*)(smb + MU_O))[t];
        const float rs = ((float*)(smb + RS_O))[t];
        const float* c1 = (const float*)(smb + C1_O);
        const float* c2 = (const float*)(smb + C2_O);
        float* lrow = lgs + t * 68;

        float mx = -1e30f, v0 = -1e30f, v1 = -1e30f;
        int i0 = 0, i1 = 0;
        #pragma unroll 8
        for (int e = 0; e < 64; ++e) {
            float v = fmaf(-mu, c1[e], lrow[e]) * rs + c2[e];
            lrow[e] = v;
            mx = fmaxf(mx, v);
            if (v > v0)      { v1 = v0; i1 = i0; v0 = v; i0 = e; }
            else if (v > v1) { v1 = v; i1 = e; }
        }
        float sum = 0.f;
        #pragma unroll 8
        for (int e = 0; e < 64; ++e) {
            float ev = __expf(lrow[e] - mx);
            lrow[e] = ev;
            sum += ev;
        }
        float inv = 1.f / sum;
        float sw0 = __expf(v0 - mx) * inv;
        float sw1 = __expf(v1 - mx) * inv;
        float rn  = 1.f / (sw0 + sw1 + 1e-8f);
        float o0 = sw0 * rn, o1 = sw1 * rn;

        int grow = row0 + t;
        float* orow = out + (size_t)grow * 64;
        #pragma unroll
        for (int e = 0; e < 64; e += 4) {
            float w0 = lrow[e + 0] * inv;
            float w1 = lrow[e + 1] * inv;
            float w2 = lrow[e + 2] * inv;
            float w3 = lrow[e + 3] * inv;
            lrow[e + 0] = w0; lrow[e + 1] = w1;
            lrow[e + 2] = w2; lrow[e + 3] = w3;
            float4 o;
            o.x = (e + 0 == i0) ? o0 : ((e + 0 == i1) ? o1 : 0.f);
            o.y = (e + 1 == i0) ? o0 : ((e + 1 == i1) ? o1 : 0.f);
            o.z = (e + 2 == i0) ? o0 : ((e + 2 == i1) ? o1 : 0.f);
            o.w = (e + 3 == i0) ? o0 : ((e + 3 == i1) ? o1 : 0.f);
            *(float4*)(orow + e) = o;
        }
        out[OUT_IDX_OFF + (size_t)grow * 2 + 0] = (float)i0;
        out[OUT_IDX_OFF + (size_t)grow * 2 + 1] = (float)i1;
    }
    __syncthreads();

    // ---- deterministic per-CTA lb partials ----
    if (t < N_EXP) {
        float s = 0.f;
        #pragma unroll 8
        for (int r = 0; r < TM; ++r) s += lgs[r * 68 + t];
        g_part[blockIdx.x * N_EXP + t] = s;
    }
}

// ================= final: load-balance loss =================
__global__ void final_kernel(float* __restrict__ out) {
    __shared__ float sh[N_EXP];
    int t = threadIdx.x;  // 64 threads
    float s = 0.f;
    for (int c = 0; c < NCTA; ++c) s += g_part[c * N_EXP + t];
    float mean = s * (1.f / ROWS);
    sh[t] = -mean * logf(mean + 1e-8f);
    __syncthreads();
    if (t == 0) {
        float acc = 0.f;
        for (int i = 0; i < N_EXP; ++i) acc += sh[i];
        out[OUT_LB_OFF] = acc;
    }
}

extern "C" void kernel_launch(void* const* d_in, const int* in_sizes, int n_in,
                              void* d_out, int out_size) {
    const float* x     = (const float*)d_in[0];
    const float* gamma = (const float*)d_in[1];
    const float* beta  = (const float*)d_in[2];
    const float* W     = (const float*)d_in[3];
    const float* b     = (const float*)d_in[4];
    float* out = (float*)d_out;

    cudaFuncSetAttribute(main_kernel, cudaFuncAttributeMaxDynamicSharedMemorySize, SMEM_REQ);

    prep_kernel<<<N_EXP, 256>>>(W, gamma, beta, b);
    main_kernel<<<NCTA, THREADS, SMEM_REQ>>>(x, out);
    final_kernel<<<1, N_EXP>>>(out);
}

// round 7
// speedup vs baseline: 2.9412x; 1.1420x over previous
#include <cuda_runtime.h>
#include <cuda_fp16.h>
#include <math.h>
#include <stdint.h>

#define D_MODEL 4096
#define N_EXP   64
#define ROWS    16384          // 4 * 4096
#define LN_EPS  1e-5f
#define TM      128            // rows per CTA
#define NSTAGE  64             // K chunks of 64
#define NCTA    (ROWS / TM)    // 128
#define THREADS 512

// Output layout (fp32 flat): sparse_w[16384*64], indices[16384*2] as float, lb_loss
#define OUT_IDX_OFF 1048576
#define OUT_LB_OFF  1081344

// ---- dynamic smem layout ----
#define A_STR 144
#define B_STR 144
#define AH_O  0
#define AM_O  18432
#define BH_O  36864
#define BM_O  46080
#define BUFB  55296
#define EXT   (2 * BUFB)          // 110592
#define MU_O  (EXT)
#define RS_O  (EXT + 512)
#define C1_O  (EXT + 1024)
#define C2_O  (EXT + 1280)
#define SMEM_REQ (EXT + 1536)     // 112128 bytes

// ---- device scratch ----
__device__ __align__(16) __half g_wh[N_EXP * D_MODEL];  // high fp16 part of gamma*W
__device__ __align__(16) __half g_wm[N_EXP * D_MODEL];  // mid  fp16 part
__device__ float g_c1[N_EXP];
__device__ float g_c2[N_EXP];
__device__ float g_part[NCTA * N_EXP];

// ================= PTX helpers =================
__device__ __forceinline__ uint32_t smem_u32(const void* p) {
    uint32_t a;
    asm("{ .reg .u64 t; cvta.to.shared.u64 t, %1; cvt.u32.u64 %0, t; }" : "=r"(a) : "l"(p));
    return a;
}
__device__ __forceinline__ void ldsm4(uint32_t* r, uint32_t addr) {
    asm volatile("ldmatrix.sync.aligned.m8n8.x4.shared.b16 {%0,%1,%2,%3}, [%4];"
                 : "=r"(r[0]), "=r"(r[1]), "=r"(r[2]), "=r"(r[3]) : "r"(addr));
}
__device__ __forceinline__ void mma16816(float* c, const uint32_t* a, const uint32_t* b) {
    asm volatile(
        "mma.sync.aligned.m16n8k16.row.col.f32.f16.f16.f32 "
        "{%0,%1,%2,%3}, {%4,%5,%6,%7}, {%8,%9}, {%0,%1,%2,%3};"
        : "+f"(c[0]), "+f"(c[1]), "+f"(c[2]), "+f"(c[3])
        : "r"(a[0]), "r"(a[1]), "r"(a[2]), "r"(a[3]), "r"(b[0]), "r"(b[1]));
}
__device__ __forceinline__ uint32_t cvt_h2(float lo, float hi) {
    uint32_t r;
    asm("cvt.rn.f16x2.f32 %0, %1, %2;" : "=r"(r) : "f"(hi), "f"(lo));
    return r;
}

// ================= prep: split gamma*W into fp16 h/m parts + c1/c2 =================
__global__ void prep_kernel(const float* __restrict__ W,
                            const float* __restrict__ gamma,
                            const float* __restrict__ beta,
                            const float* __restrict__ b) {
    int e = blockIdx.x;
    int t = threadIdx.x;   // 1024
    float a1 = 0.f, a2 = 0.f;
    #pragma unroll
    for (int i = 0; i < 4; ++i) {
        int k = i * 1024 + t;
        float w  = W[e * D_MODEL + k];
        float gw = gamma[k] * w;
        a1 += gw;
        a2 += beta[k] * w;
        __half h = __float2half_rn(gw);
        float  r = gw - __half2float(h);
        __half m = __float2half_rn(r);
        g_wh[e * D_MODEL + k] = h;
        g_wm[e * D_MODEL + k] = m;
    }
    __shared__ float s1[32], s2[32];
    #pragma unroll
    for (int o = 16; o > 0; o >>= 1) {
        a1 += __shfl_xor_sync(0xffffffffu, a1, o);
        a2 += __shfl_xor_sync(0xffffffffu, a2, o);
    }
    if ((t & 31) == 0) { s1[t >> 5] = a1; s2[t >> 5] = a2; }
    __syncthreads();
    if (t < 32) {
        float v1 = s1[t], v2 = s2[t];
        #pragma unroll
        for (int o = 16; o > 0; o >>= 1) {
            v1 += __shfl_xor_sync(0xffffffffu, v1, o);
            v2 += __shfl_xor_sync(0xffffffffu, v2, o);
        }
        if (t == 0) { g_c1[e] = v1; g_c2[e] = v2 + b[e]; }
    }
}

// ================= main fused kernel =================
extern __shared__ char smem_dyn[];

__global__ __launch_bounds__(THREADS, 1)
void main_kernel(const float* __restrict__ x, float* __restrict__ out) {
    char* smb = smem_dyn;
    const uint32_t sbase = smem_u32(smb);
    const int t    = threadIdx.x;
    const int lane = t & 31;
    const int wid  = t >> 5;
    const int wm   = wid & 7;       // M block (16 rows)
    const int wn   = wid >> 3;      // N block (32 cols)
    const int row0 = blockIdx.x * TM;

    if (t < 64) {
        ((float*)(smb + C1_O))[t] = g_c1[t];
        ((float*)(smb + C2_O))[t] = g_c2[t];
    }

    // producer mapping: 4 threads per row (16 cols each); B copier: 1 uint4/part
    const int pr = t >> 2, p4 = t & 3;
    const int brow = t >> 3, bc = t & 7;
    const float4* xp  = (const float4*)(x + (size_t)(row0 + pr) * D_MODEL + p4 * 16);
    const uint4*  bhp = (const uint4*)g_wh;
    const uint4*  bmp = (const uint4*)g_wm;

    // ldmatrix lane offsets
    const uint32_t aoff = (uint32_t)((wm * 16 + (lane & 15)) * A_STR + (lane >> 4) * 16);
    const uint32_t boff = (uint32_t)((wn * 32 + ((lane >> 4) & 1) * 8 + (lane & 7)) * B_STR
                                     + ((lane >> 3) & 1) * 16);
    const uint32_t a_sts = (uint32_t)(pr * A_STR + p4 * 32);
    const uint32_t b_sts = (uint32_t)(brow * B_STR + bc * 16);

    float acc[4][4];
    #pragma unroll
    for (int ni = 0; ni < 4; ++ni)
        #pragma unroll
        for (int q = 0; q < 4; ++q) acc[ni][q] = 0.f;

    float ls = 0.f, lss = 0.f;

    float4 cx[4];
    uint4  cbh, cbm;

    // ---- prologue: stage 0 load + split/store, prefetch stage 1 ----
    #pragma unroll
    for (int j = 0; j < 4; ++j) cx[j] = xp[j];
    cbh = bhp[(size_t)brow * 512 + bc];
    cbm = bmp[(size_t)brow * 512 + bc];

    {
        char* bb = smb;
        *(uint4*)(bb + BH_O + b_sts) = cbh;
        *(uint4*)(bb + BM_O + b_sts) = cbm;
        #pragma unroll
        for (int g = 0; g < 2; ++g) {
            float4 a = cx[2 * g], c = cx[2 * g + 1];
            float f[8] = {a.x, a.y, a.z, a.w, c.x, c.y, c.z, c.w};
            uint32_t hp[4], mp[4];
            #pragma unroll
            for (int i = 0; i < 4; ++i) {
                float f0 = f[2 * i], f1 = f[2 * i + 1];
                uint32_t h2 = cvt_h2(f0, f1);
                __half2 hh = *(__half2*)&h2;
                float2 bk = __half22float2(hh);
                mp[i] = cvt_h2(f0 - bk.x, f1 - bk.y);
                hp[i] = h2;
                ls  += f0 + f1;
                lss  = fmaf(f0, f0, fmaf(f1, f1, lss));
            }
            *(uint4*)(bb + AH_O + a_sts + g * 16) = make_uint4(hp[0], hp[1], hp[2], hp[3]);
            *(uint4*)(bb + AM_O + a_sts + g * 16) = make_uint4(mp[0], mp[1], mp[2], mp[3]);
        }
        #pragma unroll
        for (int j = 0; j < 4; ++j) cx[j] = xp[16 + j];
        cbh = bhp[(size_t)brow * 512 + 8 + bc];
        cbm = bmp[(size_t)brow * 512 + 8 + bc];
    }
    __syncthreads();

    // ---- main loop: MMA(s) || split+STS(s+1) || LDG(s+2) ----
    for (int s = 0; s < NSTAGE; ++s) {
        const uint32_t rb = sbase + (uint32_t)((s & 1) * BUFB);
        char* wbuf = smb + ((s + 1) & 1) * BUFB;

        const uint32_t abh = rb + AH_O + aoff;
        const uint32_t abm = rb + AM_O + aoff;
        const uint32_t bbh = rb + BH_O + boff;
        const uint32_t bbm = rb + BM_O + boff;

        #pragma unroll
        for (int kk = 0; kk < 4; ++kk) {
            const uint32_t kb = kk * 32;
            uint32_t ah[4], am[4];
            uint32_t bh01[4], bh23[4], bm01[4], bm23[4];
            ldsm4(ah, abh + kb);
            ldsm4(am, abm + kb);
            ldsm4(bh01, bbh + kb);
            ldsm4(bh23, bbh + 2304 + kb);
            ldsm4(bm01, bbm + kb);
            ldsm4(bm23, bbm + 2304 + kb);
            const uint32_t* bhv[4] = {bh01, bh01 + 2, bh23, bh23 + 2};
            const uint32_t* bmv[4] = {bm01, bm01 + 2, bm23, bm23 + 2};
            // product-major: accumulator reuse distance = 4 MMAs
            #pragma unroll
            for (int ni = 0; ni < 4; ++ni) mma16816(acc[ni], ah, bhv[ni]);
            #pragma unroll
            for (int ni = 0; ni < 4; ++ni) mma16816(acc[ni], ah, bmv[ni]);
            #pragma unroll
            for (int ni = 0; ni < 4; ++ni) mma16816(acc[ni], am, bhv[ni]);
        }

        if (s + 1 < NSTAGE) {
            *(uint4*)(wbuf + BH_O + b_sts) = cbh;
            *(uint4*)(wbuf + BM_O + b_sts) = cbm;
            #pragma unroll
            for (int g = 0; g < 2; ++g) {
                float4 a = cx[2 * g], c = cx[2 * g + 1];
                float f[8] = {a.x, a.y, a.z, a.w, c.x, c.y, c.z, c.w};
                uint32_t hp[4], mp[4];
                #pragma unroll
                for (int i = 0; i < 4; ++i) {
                    float f0 = f[2 * i], f1 = f[2 * i + 1];
                    uint32_t h2 = cvt_h2(f0, f1);
                    __half2 hh = *(__half2*)&h2;
                    float2 bk = __half22float2(hh);
                    mp[i] = cvt_h2(f0 - bk.x, f1 - bk.y);
                    hp[i] = h2;
                    ls  += f0 + f1;
                    lss  = fmaf(f0, f0, fmaf(f1, f1, lss));
                }
                *(uint4*)(wbuf + AH_O + a_sts + g * 16) = make_uint4(hp[0], hp[1], hp[2], hp[3]);
                *(uint4*)(wbuf + AM_O + a_sts + g * 16) = make_uint4(mp[0], mp[1], mp[2], mp[3]);
            }
        }

        if (s + 2 < NSTAGE) {
            #pragma unroll
            for (int j = 0; j < 4; ++j) cx[j] = xp[(s + 2) * 16 + j];
            cbh = bhp[(size_t)brow * 512 + (s + 2) * 8 + bc];
            cbm = bmp[(size_t)brow * 512 + (s + 2) * 8 + bc];
        }

        __syncthreads();
    }

    // ---- LN stats (reduce over 4 lanes per row) ----
    ls  += __shfl_xor_sync(0xffffffffu, ls, 1);
    ls  += __shfl_xor_sync(0xffffffffu, ls, 2);
    lss += __shfl_xor_sync(0xffffffffu, lss, 1);
    lss += __shfl_xor_sync(0xffffffffu, lss, 2);
    if (p4 == 0) {
        float mu  = ls * (1.f / D_MODEL);
        float var = lss * (1.f / D_MODEL) - mu * mu;
        ((float*)(smb + MU_O))[pr] = mu;
        ((float*)(smb + RS_O))[pr] = rsqrtf(var + LN_EPS);
    }
    __syncthreads();

    // ---- dump raw dot products to smem logits tile [128][68] ----
    float* lgs = (float*)smb;
    #pragma unroll
    for (int ni = 0; ni < 4; ++ni) {
        int row = wm * 16 + (lane >> 2);
        int col = wn * 32 + ni * 8 + (lane & 3) * 2;
        lgs[row * 68 + col]           = acc[ni][0];
        lgs[row * 68 + col + 1]       = acc[ni][1];
        lgs[(row + 8) * 68 + col]     = acc[ni][2];
        lgs[(row + 8) * 68 + col + 1] = acc[ni][3];
    }
    __syncthreads();

    // ---- per-row epilogue ----
    if (t < TM) {
        const float mu = ((float*)(smb + MU_O))[t];
        const float rs = ((float*)(smb + RS_O))[t];
        const float* c1 = (const float*)(smb + C1_O);
        const float* c2 = (const float*)(smb + C2_O);
        float* lrow = lgs + t * 68;

        float mx = -1e30f, v0 = -1e30f, v1 = -1e30f;
        int i0 = 0, i1 = 0;
        #pragma unroll 8
        for (int e = 0; e < 64; ++e) {
            float v = fmaf(-mu, c1[e], lrow[e]) * rs + c2[e];
            lrow[e] = v;
            mx = fmaxf(mx, v);
            if (v > v0)      { v1 = v0; i1 = i0; v0 = v; i0 = e; }
            else if (v > v1) { v1 = v; i1 = e; }
        }
        float sum = 0.f;
        #pragma unroll 8
        for (int e = 0; e < 64; ++e) {
            float ev = __expf(lrow[e] - mx);
            lrow[e] = ev;
            sum += ev;
        }
        float inv = 1.f / sum;
        float sw0 = __expf(v0 - mx) * inv;
        float sw1 = __expf(v1 - mx) * inv;
        float rn  = 1.f / (sw0 + sw1 + 1e-8f);
        float o0 = sw0 * rn, o1 = sw1 * rn;

        int grow = row0 + t;
        float* orow = out + (size_t)grow * 64;
        #pragma unroll
        for (int e = 0; e < 64; e += 4) {
            float w0 = lrow[e + 0] * inv;
            float w1 = lrow[e + 1] * inv;
            float w2 = lrow[e + 2] * inv;
            float w3 = lrow[e + 3] * inv;
            lrow[e + 0] = w0; lrow[e + 1] = w1;
            lrow[e + 2] = w2; lrow[e + 3] = w3;
            float4 o;
            o.x = (e + 0 == i0) ? o0 : ((e + 0 == i1) ? o1 : 0.f);
            o.y = (e + 1 == i0) ? o0 : ((e + 1 == i1) ? o1 : 0.f);
            o.z = (e + 2 == i0) ? o0 : ((e + 2 == i1) ? o1 : 0.f);
            o.w = (e + 3 == i0) ? o0 : ((e + 3 == i1) ? o1 : 0.f);
            *(float4*)(orow + e) = o;
        }
        out[OUT_IDX_OFF + (size_t)grow * 2 + 0] = (float)i0;
        out[OUT_IDX_OFF + (size_t)grow * 2 + 1] = (float)i1;
    }
    __syncthreads();

    // ---- deterministic per-CTA lb partials ----
    if (t < N_EXP) {
        float s = 0.f;
        #pragma unroll 8
        for (int r = 0; r < TM; ++r) s += lgs[r * 68 + t];
        g_part[blockIdx.x * N_EXP + t] = s;
    }
}

// ================= final: load-balance loss =================
__global__ void final_kernel(float* __restrict__ out) {
    __shared__ float sh[N_EXP];
    int t = threadIdx.x;  // 64 threads
    float s = 0.f;
    for (int c = 0; c < NCTA; ++c) s += g_part[c * N_EXP + t];
    float mean = s * (1.f / ROWS);
    sh[t] = -mean * logf(mean + 1e-8f);
    __syncthreads();
    if (t == 0) {
        float acc = 0.f;
        for (int i = 0; i < N_EXP; ++i) acc += sh[i];
        out[OUT_LB_OFF] = acc;
    }
}

extern "C" void kernel_launch(void* const* d_in, const int* in_sizes, int n_in,
                              void* d_out, int out_size) {
    const float* x     = (const float*)d_in[0];
    const float* gamma = (const float*)d_in[1];
    const float* beta  = (const float*)d_in[2];
    const float* W     = (const float*)d_in[3];
    const float* b     = (const float*)d_in[4];
    float* out = (float*)d_out;

    cudaFuncSetAttribute(main_kernel, cudaFuncAttributeMaxDynamicSharedMemorySize, SMEM_REQ);

    prep_kernel<<<N_EXP, 1024>>>(W, gamma, beta, b);
    main_kernel<<<NCTA, THREADS, SMEM_REQ>>>(x, out);
    final_kernel<<<1, N_EXP>>>(out);
}